// round 10
// baseline (speedup 1.0000x reference)
#include <cuda_runtime.h>
#include <math.h>

#define E 2048
#define NBLK 444
#define NTHR 256
#define NWARPS (NBLK * 8)
#define NSLAB 37
#define SLABSZ 56

typedef unsigned long long ull;

// ---------------- static scratch ----------------
__device__ ull        g_PN[6 * E];        // pack(exp(e2), exp(.2 e2))
__device__ ull        g_m1[6 * E];        // pack(exp(e1), exp(.2 e1))
__device__ ull        g_h01[6 * E];
__device__ ull        g_h23[6 * E];
__device__ ull        g_h45[6 * E];
__device__ ulonglong4 g_nd[6 * E];        // {m2, h01, h23, h45} merged record
__device__ float      g_part[NSLAB * 36 * E]; // [slab][cd][j]
__device__ float      g_XW[E * 32];
__device__ float      g_G1p[8 * E * 32];  // 8 k-slices
__device__ float4     g_Z[E];

// ---------------- grid barrier (spread counters, monotone, replay-safe) ----------------
__device__ unsigned g_cnt16[16 * 32];     // arrival counters, 128B apart
__device__ unsigned g_rel;                // total releases ever (monotone)

__device__ __forceinline__ void gsync(unsigned base, unsigned epoch) {
    __syncthreads();
    if (threadIdx.x == 0) {
        __threadfence();
        atomicAdd(&g_cnt16[(blockIdx.x & 15) * 32], 1u);
    }
    if (blockIdx.x == 0) {
        if (threadIdx.x < 32) {
            unsigned want = (unsigned)NBLK * (base + epoch);
            int lane = threadIdx.x;
            unsigned s;
            do {
                s = (lane < 16) ? *(volatile unsigned*)&g_cnt16[lane * 32] : 0u;
#pragma unroll
                for (int off = 16; off; off >>= 1)
                    s += __shfl_xor_sync(0xffffffffu, s, off);
            } while (s != want);
            if (lane == 0) {
                __threadfence();
                *(volatile unsigned*)&g_rel = base + epoch;
            }
        }
    } else {
        if (threadIdx.x == 0) {
            while ((*(volatile unsigned*)&g_rel) - base < epoch) __nanosleep(32);
            __threadfence();
        }
    }
    __syncthreads();
}

// ---------------- packed f32x2 helpers ----------------
__device__ __forceinline__ ull pack2(float x, float y) {
    ull r; asm("mov.b64 %0, {%1, %2};" : "=l"(r) : "f"(x), "f"(y)); return r;
}
__device__ __forceinline__ float2 unpack2(ull v) {
    float2 r; asm("mov.b64 {%0, %1}, %2;" : "=f"(r.x), "=f"(r.y) : "l"(v)); return r;
}
__device__ __forceinline__ void ffma2(ull& d, ull a, ull b) {
    asm("fma.rn.f32x2 %0, %1, %2, %0;" : "+l"(d) : "l"(a), "l"(b));
}
__device__ __forceinline__ ull mul2(ull a, ull b) {
    ull r; asm("mul.rn.f32x2 %0, %1, %2;" : "=l"(r) : "l"(a), "l"(b)); return r;
}

// ---------------- the persistent mega-kernel ----------------
__global__ void __launch_bounds__(NTHR, 3) mega(
    const float* __restrict__ node, const float* __restrict__ uv,
    const float* __restrict__ adj,
    const float* __restrict__ Wt1, const float* __restrict__ at1,
    const float* __restrict__ Wt2, const float* __restrict__ at2,
    const float* __restrict__ Wg1, const float* __restrict__ bg1,
    const float* __restrict__ Wg2, const float* __restrict__ bg2,
    const float* __restrict__ Wo1, const float* __restrict__ bo1,
    const float* __restrict__ Wo2, const float* __restrict__ bo2,
    float* __restrict__ out)
{
    __shared__ float s_u[8192];           // 32 KB (regs limit occupancy, not smem)
    int tid = threadIdx.x;
    int bid = blockIdx.x;
    int lane = tid & 31;
    int gwarp = bid * 8 + (tid >> 5);
    unsigned base = *(volatile unsigned*)&g_rel;   // stable between replays

    // ===== phase 1: per-node h + factor pairs =====
    for (int idx = bid * NTHR + tid; idx < 6 * E; idx += NBLK * NTHR) {
        int c = idx >> 11, i = idx & 2047;
        int g = (c >= 3);
        int t = g ? c - 3 : c;
        const float* W  = (g ? Wt2 : Wt1) + t * 192;
        const float* av = (g ? at2 : at1) + t * 12;
        const float* xr = (g ? uv : node) + i * 32;   // batch 0
        float h[6] = {0.f, 0.f, 0.f, 0.f, 0.f, 0.f};
#pragma unroll
        for (int k = 0; k < 32; k++) {
            float xk = __ldg(&xr[k]);
#pragma unroll
            for (int d = 0; d < 6; d++) h[d] = fmaf(xk, __ldg(&W[k * 6 + d]), h[d]);
        }
        float e1 = 0.f, e2 = 0.f;
#pragma unroll
        for (int d = 0; d < 6; d++) {
            e1 = fmaf(h[d], __ldg(&av[d]), e1);
            e2 = fmaf(h[d], __ldg(&av[6 + d]), e2);
        }
        int gi = c * E + i;
        g_m1[gi]  = pack2(__expf(e1), __expf(0.2f * e1));
        g_PN[gi]  = pack2(__expf(e2), __expf(0.2f * e2));
        g_h01[gi] = pack2(h[0], h[1]);
        g_h23[gi] = pack2(h[2], h[3]);
        g_h45[gi] = pack2(h[4], h[5]);
    }
    gsync(base, 1);

    // ===== phase 2: softmax row denominators (warp per row, 6 combos) =====
    for (int r = gwarp; r < E; r += NWARPS) {
        ull mk[6]; float acc[6];
#pragma unroll
        for (int c = 0; c < 6; c++) { mk[c] = g_m1[c * E + r]; acc[c] = 0.f; }
        const float* arow = &adj[(size_t)r * E];
        for (int it = 0; it < 16; it++) {
            int j = it * 128 + lane * 4;
            float4 av = *(const float4*)&arow[j];
#pragma unroll
            for (int c = 0; c < 6; c++) {
                ulonglong2 pn01 = *(const ulonglong2*)&g_PN[c * E + j];
                ulonglong2 pn23 = *(const ulonglong2*)&g_PN[c * E + j + 2];
                float2 t;
                t = unpack2(mul2(mk[c], pn01.x)); acc[c] = fmaf(av.x, fmaxf(t.x, t.y), acc[c]);
                t = unpack2(mul2(mk[c], pn01.y)); acc[c] = fmaf(av.y, fmaxf(t.x, t.y), acc[c]);
                t = unpack2(mul2(mk[c], pn23.x)); acc[c] = fmaf(av.z, fmaxf(t.x, t.y), acc[c]);
                t = unpack2(mul2(mk[c], pn23.y)); acc[c] = fmaf(av.w, fmaxf(t.x, t.y), acc[c]);
            }
        }
#pragma unroll
        for (int c = 0; c < 6; c++) {
            float v = acc[c];
            for (int off = 16; off; off >>= 1) v += __shfl_down_sync(0xffffffffu, v, off);
            if (lane == 0) {
                float inv = 1.0f / v;
                float2 m = unpack2(mk[c]);
                ulonglong4 nd;
                nd.x = pack2(m.x * inv, m.y * inv);
                nd.y = g_h01[c * E + r];
                nd.z = g_h23[c * E + r];
                nd.w = g_h45[c * E + r];
                g_nd[c * E + r] = nd;
            }
        }
    }
    gsync(base, 2);

    // ===== phase 3: attention aggregation (3552 warp-tasks, 1 per warp) =====
    for (int task = gwarp; task < 96 * NSLAB; task += NWARPS) {
        int c    = task % 6;
        int jt   = (task / 6) % 16;
        int slab = task / 96;
        int j0 = jt * 128 + lane * 4;
        int ib = slab * SLABSZ;
        int iend = ib + SLABSZ; if (iend > E) iend = E;

        ull PN[4];
#pragma unroll
        for (int q = 0; q < 4; q++) PN[q] = __ldg(&g_PN[c * E + j0 + q]);

        ull acc[12];
#pragma unroll
        for (int q = 0; q < 12; q++) acc[q] = 0;

#pragma unroll 1
        for (int ii = ib; ii < iend; ii += 4) {
            float4 av[4];
#pragma unroll
            for (int u = 0; u < 4; u++)
                av[u] = *(const float4*)&adj[(size_t)(ii + u) * E + j0];
#pragma unroll
            for (int h = 0; h < 2; h++) {
                ulonglong4 nd0 = g_nd[c * E + ii + h * 2 + 0];
                ulonglong4 nd1 = g_nd[c * E + ii + h * 2 + 1];
#pragma unroll
                for (int u = 0; u < 2; u++) {
                    ulonglong4 nd = u ? nd1 : nd0;
                    const float* af = (const float*)&av[h * 2 + u];
#pragma unroll
                    for (int q = 0; q < 4; q++) {
                        float2 t = unpack2(mul2(nd.x, PN[q]));
                        float w = fmaxf(t.x, t.y) * af[q];
                        ull wp = pack2(w, w);
                        ffma2(acc[q * 3 + 0], wp, nd.y);
                        ffma2(acc[q * 3 + 1], wp, nd.z);
                        ffma2(acc[q * 3 + 2], wp, nd.w);
                    }
                }
            }
        }

        int bse = slab * 36 + c * 6;
#pragma unroll
        for (int p = 0; p < 3; p++) {
            float2 t0 = unpack2(acc[p]), t1 = unpack2(acc[3 + p]);
            float2 t2 = unpack2(acc[6 + p]), t3 = unpack2(acc[9 + p]);
            *(float4*)&g_part[(size_t)(bse + 2 * p) * E + j0] =
                make_float4(t0.x, t1.x, t2.x, t3.x);
            *(float4*)&g_part[(size_t)(bse + 2 * p + 1) * E + j0] =
                make_float4(t0.y, t1.y, t2.y, t3.y);
        }
    }
    gsync(base, 3);

    // ===== phase 4: slab-reduce + ELU + XW  (64 tiles) =====
    for (int tile = bid; tile < 64; tile += NBLK) {
        int j0 = tile * 32;
        float* sh = s_u;              // [36][33]
        float* sW0 = s_u + 1188;      // 288
        float* sW1 = s_u + 1476;      // 288
        for (int t = tid; t < 288; t += NTHR) {
            sW0[t] = __ldg(&Wg1[t]);
            sW1[t] = __ldg(&Wo1[t]);
        }
        for (int t = tid; t < 36 * 32; t += NTHR) {
            int cd = t >> 5, jj = t & 31;
            int j = j0 + jj;
            float s = 0.f;
            for (int sl = 0; sl < NSLAB; sl++)
                s += g_part[(size_t)(sl * 36 + cd) * E + j];
            sh[cd * 33 + jj] = s > 0.f ? s : expm1f(s);
        }
        __syncthreads();
        for (int o = tid; o < 1024; o += NTHR) {
            int c = o >> 5, jj = o & 31;
            int g = c >> 4, cc = c & 15;
            const float* sW = g ? sW1 : sW0;
            float s = 0.f;
#pragma unroll
            for (int k = 0; k < 18; k++)
                s = fmaf(sh[(g * 18 + k) * 33 + jj], sW[k * 16 + cc], s);
            g_XW[(j0 + jj) * 32 + c] = s;
        }
        __syncthreads();
    }
    gsync(base, 4);

    // ===== phase 5: a0 @ XW  (256 block-tasks: 32 r-tiles x 8 k-slices) =====
    for (int task = bid; task < 256; task += NBLK) {
        int r0 = (task & 31) * 64;
        int ks = task >> 5;
        float* As = s_u;              // [64][33]
        float* Bs = s_u + 2112;       // [32][32]
        int rl = tid >> 2, cg = (tid & 3) * 8;
        int kc = tid & 31, rr = tid >> 5;
        float acc[8];
#pragma unroll
        for (int u = 0; u < 8; u++) acc[u] = 0.f;

        for (int kt = 0; kt < 8; kt++) {
            int kb = ks * 256 + kt * 32;
            __syncthreads();
#pragma unroll
            for (int p = 0; p < 8; p++)
                As[(rr + p * 8) * 33 + kc] = adj[(size_t)(r0 + rr + p * 8) * E + kb + kc];
#pragma unroll
            for (int p = 0; p < 4; p++)
                Bs[(rr + p * 8) * 32 + kc] = g_XW[(kb + rr + p * 8) * 32 + kc];
            __syncthreads();
#pragma unroll
            for (int kk = 0; kk < 32; kk++) {
                float a = As[rl * 33 + kk];
                const float4* b = (const float4*)&Bs[kk * 32 + cg];
                float4 b0 = b[0], b1 = b[1];
                acc[0] = fmaf(a, b0.x, acc[0]);
                acc[1] = fmaf(a, b0.y, acc[1]);
                acc[2] = fmaf(a, b0.z, acc[2]);
                acc[3] = fmaf(a, b0.w, acc[3]);
                acc[4] = fmaf(a, b1.x, acc[4]);
                acc[5] = fmaf(a, b1.y, acc[5]);
                acc[6] = fmaf(a, b1.z, acc[6]);
                acc[7] = fmaf(a, b1.w, acc[7]);
            }
        }
        float* dst = &g_G1p[((size_t)ks * E + r0 + rl) * 32 + cg];
        ((float4*)dst)[0] = make_float4(acc[0], acc[1], acc[2], acc[3]);
        ((float4*)dst)[1] = make_float4(acc[4], acc[5], acc[6], acc[7]);
        __syncthreads();
    }
    gsync(base, 5);

    // ===== phase 6: k-slice reduce + bias/relu + layer-2 weights =====
    for (int j = bid * NTHR + tid; j < E; j += NBLK * NTHR) {
        float y[32];
#pragma unroll
        for (int c4 = 0; c4 < 8; c4++) {
            float4 s = make_float4(0.f, 0.f, 0.f, 0.f);
#pragma unroll
            for (int ks = 0; ks < 8; ks++) {
                float4 v = *(const float4*)&g_G1p[((size_t)ks * E + j) * 32 + c4 * 4];
                s.x += v.x; s.y += v.y; s.z += v.z; s.w += v.w;
            }
            y[c4 * 4 + 0] = s.x; y[c4 * 4 + 1] = s.y;
            y[c4 * 4 + 2] = s.z; y[c4 * 4 + 3] = s.w;
        }
#pragma unroll
        for (int c = 0; c < 16; c++) {
            float a = y[c] + __ldg(&bg1[c]);
            y[c] = a > 0.f ? a : 0.f;
            float b = y[16 + c] + __ldg(&bo1[c]);
            y[16 + c] = b > 0.f ? b : 0.f;
        }
        float z0 = 0.f, z1 = 0.f, z2 = 0.f, z3 = 0.f;
#pragma unroll
        for (int k = 0; k < 16; k++) {
            z0 = fmaf(y[k], __ldg(&Wg2[k * 2 + 0]), z0);
            z1 = fmaf(y[k], __ldg(&Wg2[k * 2 + 1]), z1);
            z2 = fmaf(y[16 + k], __ldg(&Wo2[k * 2 + 0]), z2);
            z3 = fmaf(y[16 + k], __ldg(&Wo2[k * 2 + 1]), z3);
        }
        g_Z[j] = make_float4(z0, z1, z2, z3);
    }
    gsync(base, 6);

    // ===== phase 7: a0 @ Z + bias, log_softmax / leaky (Z staged in smem) =====
    {
        float4* sZ = (float4*)s_u;    // 2048 float4 = 32 KB
        for (int t = tid; t < E; t += NTHR) sZ[t] = g_Z[t];
        __syncthreads();
        for (int r = gwarp; r < E; r += NWARPS) {
            float a0 = 0.f, a1 = 0.f, a2 = 0.f, a3 = 0.f;
            const float* arow = &adj[(size_t)r * E];
#pragma unroll 1
            for (int q = 0; q < 64; q += 4) {
                float av[4];
#pragma unroll
                for (int u = 0; u < 4; u++) av[u] = arow[(q + u) * 32 + lane];
#pragma unroll
                for (int u = 0; u < 4; u++) {
                    float4 z = sZ[(q + u) * 32 + lane];
                    a0 = fmaf(av[u], z.x, a0);
                    a1 = fmaf(av[u], z.y, a1);
                    a2 = fmaf(av[u], z.z, a2);
                    a3 = fmaf(av[u], z.w, a3);
                }
            }
            for (int off = 16; off; off >>= 1) {
                a0 += __shfl_down_sync(0xffffffffu, a0, off);
                a1 += __shfl_down_sync(0xffffffffu, a1, off);
                a2 += __shfl_down_sync(0xffffffffu, a2, off);
                a3 += __shfl_down_sync(0xffffffffu, a3, off);
            }
            if (lane == 0) {
                float y0 = a0 + __ldg(&bg2[0]), y1 = a1 + __ldg(&bg2[1]);
                float m = fmaxf(y0, y1);
                float l = m + logf(expf(y0 - m) + expf(y1 - m));
                out[r * 2 + 0] = y0 - l;
                out[r * 2 + 1] = y1 - l;
                float o0 = a2 + __ldg(&bo2[0]), o1 = a3 + __ldg(&bo2[1]);
                out[2 * E + r * 2 + 0] = o0 > 0.f ? o0 : 0.01f * o0;
                out[2 * E + r * 2 + 1] = o1 > 0.f ? o1 : 0.01f * o1;
            }
        }
    }
}

// ---------------- launch ----------------
extern "C" void kernel_launch(void* const* d_in, const int* in_sizes, int n_in,
                              void* d_out, int out_size)
{
    (void)in_sizes; (void)n_in; (void)out_size;
    mega<<<NBLK, NTHR>>>(
        (const float*)d_in[0], (const float*)d_in[1], (const float*)d_in[2],
        (const float*)d_in[3], (const float*)d_in[4],
        (const float*)d_in[5], (const float*)d_in[6],
        (const float*)d_in[7], (const float*)d_in[8],
        (const float*)d_in[9], (const float*)d_in[10],
        (const float*)d_in[11], (const float*)d_in[12],
        (const float*)d_in[13], (const float*)d_in[14],
        (float*)d_out);
}

// round 11
// speedup vs baseline: 1.0457x; 1.0457x over previous
#include <cuda_runtime.h>
#include <math.h>

#define E 2048
#define NBLK 592
#define NTHR 256
#define NWARPS (NBLK * 8)
#define NSLAB 24

typedef unsigned long long ull;

// ---------------- static scratch ----------------
__device__ ull        g_PN[6 * E];        // pack(exp(e2), exp(.2 e2))
__device__ ull        g_m1[6 * E];        // pack(exp(e1), exp(.2 e1))
__device__ ull        g_h01[6 * E];
__device__ ull        g_h23[6 * E];
__device__ ull        g_h45[6 * E];
__device__ ulonglong4 g_nd[6 * E];        // {m2, h01, h23, h45}
__device__ float      g_part[NSLAB * 36 * E]; // [slab][cd][j]
__device__ float      g_XW[E * 32];
__device__ float      g_G1p[16 * E * 32]; // 16 k-slices
__device__ float4     g_Z[E];

// ---------------- grid barrier (spread counters, monotone, replay-safe) ----------------
__device__ unsigned g_cnt16[16 * 32];
__device__ unsigned g_rel;

__device__ __forceinline__ void gsync(unsigned base, unsigned epoch) {
    __syncthreads();
    if (threadIdx.x == 0) {
        __threadfence();
        atomicAdd(&g_cnt16[(blockIdx.x & 15) * 32], 1u);
    }
    if (blockIdx.x == 0) {
        if (threadIdx.x < 32) {
            unsigned want = (unsigned)NBLK * (base + epoch);
            int lane = threadIdx.x;
            unsigned s;
            do {
                s = (lane < 16) ? *(volatile unsigned*)&g_cnt16[lane * 32] : 0u;
#pragma unroll
                for (int off = 16; off; off >>= 1)
                    s += __shfl_xor_sync(0xffffffffu, s, off);
            } while (s != want);
            if (lane == 0) {
                __threadfence();
                *(volatile unsigned*)&g_rel = base + epoch;
            }
        }
    } else {
        if (threadIdx.x == 0) {
            while ((*(volatile unsigned*)&g_rel) - base < epoch) __nanosleep(32);
            __threadfence();
        }
    }
    __syncthreads();
}

// ---------------- packed f32x2 helpers ----------------
__device__ __forceinline__ ull pack2(float x, float y) {
    ull r; asm("mov.b64 %0, {%1, %2};" : "=l"(r) : "f"(x), "f"(y)); return r;
}
__device__ __forceinline__ float2 unpack2(ull v) {
    float2 r; asm("mov.b64 {%0, %1}, %2;" : "=f"(r.x), "=f"(r.y) : "l"(v)); return r;
}
__device__ __forceinline__ void ffma2(ull& d, ull a, ull b) {
    asm("fma.rn.f32x2 %0, %1, %2, %0;" : "+l"(d) : "l"(a), "l"(b));
}
__device__ __forceinline__ ull mul2(ull a, ull b) {
    ull r; asm("mul.rn.f32x2 %0, %1, %2;" : "=l"(r) : "l"(a), "l"(b)); return r;
}

// ---------------- the persistent mega-kernel ----------------
__global__ void __launch_bounds__(NTHR, 4) mega(
    const float* __restrict__ node, const float* __restrict__ uv,
    const float* __restrict__ adj,
    const float* __restrict__ Wt1, const float* __restrict__ at1,
    const float* __restrict__ Wt2, const float* __restrict__ at2,
    const float* __restrict__ Wg1, const float* __restrict__ bg1,
    const float* __restrict__ Wg2, const float* __restrict__ bg2,
    const float* __restrict__ Wo1, const float* __restrict__ bo1,
    const float* __restrict__ Wo2, const float* __restrict__ bo2,
    float* __restrict__ out)
{
    __shared__ float s_u[8192];           // 32 KB
    int tid = threadIdx.x;
    int bid = blockIdx.x;
    int lane = tid & 31;
    int gwarp = bid * 8 + (tid >> 5);
    unsigned base = *(volatile unsigned*)&g_rel;

    // ===== phase 1: per-node h + factor pairs =====
    for (int idx = bid * NTHR + tid; idx < 6 * E; idx += NBLK * NTHR) {
        int c = idx >> 11, i = idx & 2047;
        int g = (c >= 3);
        int t = g ? c - 3 : c;
        const float* W  = (g ? Wt2 : Wt1) + t * 192;
        const float* av = (g ? at2 : at1) + t * 12;
        const float4* xv = (const float4*)((g ? uv : node) + i * 32);  // batch 0
        float h[6] = {0.f, 0.f, 0.f, 0.f, 0.f, 0.f};
#pragma unroll
        for (int k4 = 0; k4 < 8; k4++) {
            float4 xq = __ldg(&xv[k4]);
            const float* xf = (const float*)&xq;
#pragma unroll
            for (int q = 0; q < 4; q++) {
                int k = k4 * 4 + q;
#pragma unroll
                for (int d = 0; d < 6; d++)
                    h[d] = fmaf(xf[q], __ldg(&W[k * 6 + d]), h[d]);
            }
        }
        float e1 = 0.f, e2 = 0.f;
#pragma unroll
        for (int d = 0; d < 6; d++) {
            e1 = fmaf(h[d], __ldg(&av[d]), e1);
            e2 = fmaf(h[d], __ldg(&av[6 + d]), e2);
        }
        int gi = c * E + i;
        g_m1[gi]  = pack2(__expf(e1), __expf(0.2f * e1));
        g_PN[gi]  = pack2(__expf(e2), __expf(0.2f * e2));
        g_h01[gi] = pack2(h[0], h[1]);
        g_h23[gi] = pack2(h[2], h[3]);
        g_h45[gi] = pack2(h[4], h[5]);
    }
    gsync(base, 1);

    // ===== phase 2: softmax denominators (4096 tasks: row x half-combo) =====
    for (int task = gwarp; task < 4096; task += NWARPS) {
        int r  = task >> 1;
        int c0 = (task & 1) * 3;
        ull mk[3]; float acc[3];
#pragma unroll
        for (int cc = 0; cc < 3; cc++) { mk[cc] = g_m1[(c0 + cc) * E + r]; acc[cc] = 0.f; }
        const float* arow = &adj[(size_t)r * E];
        for (int it = 0; it < 16; it++) {
            int j = it * 128 + lane * 4;
            float4 av = *(const float4*)&arow[j];
#pragma unroll
            for (int cc = 0; cc < 3; cc++) {
                int c = c0 + cc;
                ulonglong2 pn01 = *(const ulonglong2*)&g_PN[c * E + j];
                ulonglong2 pn23 = *(const ulonglong2*)&g_PN[c * E + j + 2];
                float2 t;
                t = unpack2(mul2(mk[cc], pn01.x)); acc[cc] = fmaf(av.x, fmaxf(t.x, t.y), acc[cc]);
                t = unpack2(mul2(mk[cc], pn01.y)); acc[cc] = fmaf(av.y, fmaxf(t.x, t.y), acc[cc]);
                t = unpack2(mul2(mk[cc], pn23.x)); acc[cc] = fmaf(av.z, fmaxf(t.x, t.y), acc[cc]);
                t = unpack2(mul2(mk[cc], pn23.y)); acc[cc] = fmaf(av.w, fmaxf(t.x, t.y), acc[cc]);
            }
        }
#pragma unroll
        for (int cc = 0; cc < 3; cc++) {
            float v = acc[cc];
            for (int off = 16; off; off >>= 1) v += __shfl_down_sync(0xffffffffu, v, off);
            if (lane == 0) {
                int c = c0 + cc;
                float inv = 1.0f / v;
                float2 m = unpack2(mk[cc]);
                ulonglong4 nd;
                nd.x = pack2(m.x * inv, m.y * inv);
                nd.y = g_h01[c * E + r];
                nd.z = g_h23[c * E + r];
                nd.w = g_h45[c * E + r];
                g_nd[c * E + r] = nd;
            }
        }
    }
    gsync(base, 2);

    // ===== phase 3: attention aggregation (4608 tasks: 6c x 32jt x 24 slabs) =====
    for (int task = gwarp; task < 4608; task += NWARPS) {
        int c    = task % 6;
        int jt   = (task / 6) & 31;
        int slab = task / 192;
        int j0 = jt * 64 + lane * 2;
        int ib = slab * 84;
        int iend = (slab == 23) ? 2048 : ib + 84;

        ull PNa = __ldg(&g_PN[c * E + j0]);
        ull PNb = __ldg(&g_PN[c * E + j0 + 1]);

        ull acc[6];
#pragma unroll
        for (int q = 0; q < 6; q++) acc[q] = 0;

#pragma unroll 1
        for (int ii = ib; ii < iend; ii += 4) {
            float2 av[4];
#pragma unroll
            for (int u = 0; u < 4; u++)
                av[u] = *(const float2*)&adj[(size_t)(ii + u) * E + j0];
#pragma unroll
            for (int u = 0; u < 4; u++) {
                ulonglong4 nd = g_nd[c * E + ii + u];
                float2 t0 = unpack2(mul2(nd.x, PNa));
                float w0 = fmaxf(t0.x, t0.y) * av[u].x;
                ull w0p = pack2(w0, w0);
                ffma2(acc[0], w0p, nd.y);
                ffma2(acc[1], w0p, nd.z);
                ffma2(acc[2], w0p, nd.w);
                float2 t1 = unpack2(mul2(nd.x, PNb));
                float w1 = fmaxf(t1.x, t1.y) * av[u].y;
                ull w1p = pack2(w1, w1);
                ffma2(acc[3], w1p, nd.y);
                ffma2(acc[4], w1p, nd.z);
                ffma2(acc[5], w1p, nd.w);
            }
        }

        int bse = slab * 36 + c * 6;
#pragma unroll
        for (int p = 0; p < 3; p++) {
            float2 tj0 = unpack2(acc[p]), tj1 = unpack2(acc[3 + p]);
            *(float2*)&g_part[(size_t)(bse + 2 * p) * E + j0]     = make_float2(tj0.x, tj1.x);
            *(float2*)&g_part[(size_t)(bse + 2 * p + 1) * E + j0] = make_float2(tj0.y, tj1.y);
        }
    }
    gsync(base, 3);

    // ===== phase 4: slab-reduce + ELU + XW  (64 tiles) =====
    for (int tile = bid; tile < 64; tile += NBLK) {
        int j0 = tile * 32;
        float* sh = s_u;              // [36][33]
        float* sW0 = s_u + 1188;
        float* sW1 = s_u + 1476;
        for (int t = tid; t < 288; t += NTHR) {
            sW0[t] = __ldg(&Wg1[t]);
            sW1[t] = __ldg(&Wo1[t]);
        }
        for (int t = tid; t < 36 * 32; t += NTHR) {
            int cd = t >> 5, jj = t & 31;
            int j = j0 + jj;
            float s = 0.f;
            for (int sl = 0; sl < NSLAB; sl++)
                s += g_part[(size_t)(sl * 36 + cd) * E + j];
            sh[cd * 33 + jj] = s > 0.f ? s : expm1f(s);
        }
        __syncthreads();
        for (int o = tid; o < 1024; o += NTHR) {
            int c = o >> 5, jj = o & 31;
            int g = c >> 4, cc = c & 15;
            const float* sW = g ? sW1 : sW0;
            float s = 0.f;
#pragma unroll
            for (int k = 0; k < 18; k++)
                s = fmaf(sh[(g * 18 + k) * 33 + jj], sW[k * 16 + cc], s);
            g_XW[(j0 + jj) * 32 + c] = s;
        }
        __syncthreads();
    }
    gsync(base, 4);

    // ===== phase 5: a0 @ XW  (512 block-tasks: 32 r-tiles x 16 k-slices) =====
    for (int task = bid; task < 512; task += NBLK) {
        int r0 = (task & 31) * 64;
        int ks = task >> 5;
        float* As = s_u;              // [64][33]
        float* Bs = s_u + 2112;       // [32][32]
        int rl = tid >> 2, cg = (tid & 3) * 8;
        int kc = tid & 31, rr = tid >> 5;
        float acc[8];
#pragma unroll
        for (int u = 0; u < 8; u++) acc[u] = 0.f;

        for (int kt = 0; kt < 4; kt++) {
            int kb = ks * 128 + kt * 32;
            __syncthreads();
#pragma unroll
            for (int p = 0; p < 8; p++)
                As[(rr + p * 8) * 33 + kc] = adj[(size_t)(r0 + rr + p * 8) * E + kb + kc];
#pragma unroll
            for (int p = 0; p < 4; p++)
                Bs[(rr + p * 8) * 32 + kc] = g_XW[(kb + rr + p * 8) * 32 + kc];
            __syncthreads();
#pragma unroll
            for (int kk = 0; kk < 32; kk++) {
                float a = As[rl * 33 + kk];
                const float4* b = (const float4*)&Bs[kk * 32 + cg];
                float4 b0 = b[0], b1 = b[1];
                acc[0] = fmaf(a, b0.x, acc[0]);
                acc[1] = fmaf(a, b0.y, acc[1]);
                acc[2] = fmaf(a, b0.z, acc[2]);
                acc[3] = fmaf(a, b0.w, acc[3]);
                acc[4] = fmaf(a, b1.x, acc[4]);
                acc[5] = fmaf(a, b1.y, acc[5]);
                acc[6] = fmaf(a, b1.z, acc[6]);
                acc[7] = fmaf(a, b1.w, acc[7]);
            }
        }
        float* dst = &g_G1p[((size_t)ks * E + r0 + rl) * 32 + cg];
        ((float4*)dst)[0] = make_float4(acc[0], acc[1], acc[2], acc[3]);
        ((float4*)dst)[1] = make_float4(acc[4], acc[5], acc[6], acc[7]);
        __syncthreads();
    }
    gsync(base, 5);

    // ===== phase 6: warp-per-j k-slice reduce + bias/relu + layer-2 =====
    for (int j = gwarp; j < E; j += NWARPS) {
        float y = 0.f;
#pragma unroll
        for (int ks = 0; ks < 16; ks++)
            y += g_G1p[((size_t)ks * E + j) * 32 + lane];
        y += (lane < 16) ? __ldg(&bg1[lane]) : __ldg(&bo1[lane - 16]);
        y = y > 0.f ? y : 0.f;
        int cc = lane & 15;
        const float* W2 = (lane < 16) ? Wg2 : Wo2;
        float zA = y * __ldg(&W2[cc * 2]);
        float zB = y * __ldg(&W2[cc * 2 + 1]);
#pragma unroll
        for (int off = 8; off; off >>= 1) {
            zA += __shfl_xor_sync(0xffffffffu, zA, off);
            zB += __shfl_xor_sync(0xffffffffu, zB, off);
        }
        if (lane == 0)  ((float2*)&g_Z[j])[0] = make_float2(zA, zB);
        if (lane == 16) ((float2*)&g_Z[j])[1] = make_float2(zA, zB);
    }
    gsync(base, 6);

    // ===== phase 7: a0 @ Z + bias, log_softmax / leaky (Z staged in smem) =====
    {
        float4* sZ = (float4*)s_u;    // 2048 float4 = 32 KB
        for (int t = tid; t < E; t += NTHR) sZ[t] = g_Z[t];
        __syncthreads();
        for (int r = gwarp; r < E; r += NWARPS) {
            float a0 = 0.f, a1 = 0.f, a2 = 0.f, a3 = 0.f;
            const float* arow = &adj[(size_t)r * E];
#pragma unroll 1
            for (int q = 0; q < 64; q += 4) {
                float av[4];
#pragma unroll
                for (int u = 0; u < 4; u++) av[u] = arow[(q + u) * 32 + lane];
#pragma unroll
                for (int u = 0; u < 4; u++) {
                    float4 z = sZ[(q + u) * 32 + lane];
                    a0 = fmaf(av[u], z.x, a0);
                    a1 = fmaf(av[u], z.y, a1);
                    a2 = fmaf(av[u], z.z, a2);
                    a3 = fmaf(av[u], z.w, a3);
                }
            }
            for (int off = 16; off; off >>= 1) {
                a0 += __shfl_down_sync(0xffffffffu, a0, off);
                a1 += __shfl_down_sync(0xffffffffu, a1, off);
                a2 += __shfl_down_sync(0xffffffffu, a2, off);
                a3 += __shfl_down_sync(0xffffffffu, a3, off);
            }
            if (lane == 0) {
                float y0 = a0 + __ldg(&bg2[0]), y1 = a1 + __ldg(&bg2[1]);
                float m = fmaxf(y0, y1);
                float l = m + logf(expf(y0 - m) + expf(y1 - m));
                out[r * 2 + 0] = y0 - l;
                out[r * 2 + 1] = y1 - l;
                float o0 = a2 + __ldg(&bo2[0]), o1 = a3 + __ldg(&bo2[1]);
                out[2 * E + r * 2 + 0] = o0 > 0.f ? o0 : 0.01f * o0;
                out[2 * E + r * 2 + 1] = o1 > 0.f ? o1 : 0.01f * o1;
            }
        }
    }
}

// ---------------- launch ----------------
extern "C" void kernel_launch(void* const* d_in, const int* in_sizes, int n_in,
                              void* d_out, int out_size)
{
    (void)in_sizes; (void)n_in; (void)out_size;
    mega<<<NBLK, NTHR>>>(
        (const float*)d_in[0], (const float*)d_in[1], (const float*)d_in[2],
        (const float*)d_in[3], (const float*)d_in[4],
        (const float*)d_in[5], (const float*)d_in[6],
        (const float*)d_in[7], (const float*)d_in[8],
        (const float*)d_in[9], (const float*)d_in[10],
        (const float*)d_in[11], (const float*)d_in[12],
        (const float*)d_in[13], (const float*)d_in[14],
        (float*)d_out);
}

// round 12
// speedup vs baseline: 1.1524x; 1.1020x over previous
#include <cuda_runtime.h>
#include <math.h>

#define E 2048
#define NBLK 592
#define NTHR 256
#define NWARPS (NBLK * 8)
#define NSLAB 24

typedef unsigned long long ull;

// ---------------- static scratch ----------------
__device__ unsigned   g_bits[E * 64];     // adj bitmask, row-major, 64 words/row
__device__ ull        g_PN[6 * E];        // pack(exp(e2), exp(.2 e2))
__device__ ull        g_m1[6 * E];        // pack(exp(e1), exp(.2 e1))
__device__ ull        g_h01[6 * E];
__device__ ull        g_h23[6 * E];
__device__ ull        g_h45[6 * E];
__device__ ulonglong4 g_nd[6 * E];        // {m2, h01, h23, h45}
__device__ float      g_part[NSLAB * 36 * E];
__device__ float      g_XW[E * 32];
__device__ float      g_G1p[32 * E * 32]; // 32 k-slices
__device__ float4     g_Z[E];

// ---------------- grid barrier (spread counters, monotone, replay-safe) ----------------
__device__ unsigned g_cnt16[16 * 32];
__device__ unsigned g_rel;

__device__ __forceinline__ void gsync(unsigned base, unsigned epoch) {
    __syncthreads();
    if (threadIdx.x == 0) {
        __threadfence();
        atomicAdd(&g_cnt16[(blockIdx.x & 15) * 32], 1u);
    }
    if (blockIdx.x == 0) {
        if (threadIdx.x < 32) {
            unsigned want = (unsigned)NBLK * (base + epoch);
            int lane = threadIdx.x;
            unsigned s;
            do {
                s = (lane < 16) ? *(volatile unsigned*)&g_cnt16[lane * 32] : 0u;
#pragma unroll
                for (int off = 16; off; off >>= 1)
                    s += __shfl_xor_sync(0xffffffffu, s, off);
            } while (s != want);
            if (lane == 0) {
                __threadfence();
                *(volatile unsigned*)&g_rel = base + epoch;
            }
        }
    } else {
        if (threadIdx.x == 0) {
            while ((*(volatile unsigned*)&g_rel) - base < epoch) __nanosleep(32);
            __threadfence();
        }
    }
    __syncthreads();
}

// ---------------- packed f32x2 helpers ----------------
__device__ __forceinline__ ull pack2(float x, float y) {
    ull r; asm("mov.b64 %0, {%1, %2};" : "=l"(r) : "f"(x), "f"(y)); return r;
}
__device__ __forceinline__ float2 unpack2(ull v) {
    float2 r; asm("mov.b64 {%0, %1}, %2;" : "=f"(r.x), "=f"(r.y) : "l"(v)); return r;
}
__device__ __forceinline__ void ffma2(ull& d, ull a, ull b) {
    asm("fma.rn.f32x2 %0, %1, %2, %0;" : "+l"(d) : "l"(a), "l"(b));
}
__device__ __forceinline__ ull mul2(ull a, ull b) {
    ull r; asm("mul.rn.f32x2 %0, %1, %2;" : "=l"(r) : "l"(a), "l"(b)); return r;
}

// ---------------- the persistent mega-kernel ----------------
__global__ void __launch_bounds__(NTHR, 4) mega(
    const float* __restrict__ node, const float* __restrict__ uv,
    const float* __restrict__ adj,
    const float* __restrict__ Wt1, const float* __restrict__ at1,
    const float* __restrict__ Wt2, const float* __restrict__ at2,
    const float* __restrict__ Wg1, const float* __restrict__ bg1,
    const float* __restrict__ Wg2, const float* __restrict__ bg2,
    const float* __restrict__ Wo1, const float* __restrict__ bo1,
    const float* __restrict__ Wo2, const float* __restrict__ bo2,
    float* __restrict__ out)
{
    __shared__ float s_u[8192];           // 32 KB
    int tid = threadIdx.x;
    int bid = blockIdx.x;
    int lane = tid & 31;
    int gwarp = bid * 8 + (tid >> 5);
    unsigned base = *(volatile unsigned*)&g_rel;

    // ===== phase 1a: bit-pack adjacency (warp ballots, 4 words/iter) =====
    for (int w = gwarp * 4; w < E * 64; w += NWARPS * 4) {
        float a0 = adj[(size_t)w * 32 + lane];
        float a1 = adj[(size_t)(w + 1) * 32 + lane];
        float a2 = adj[(size_t)(w + 2) * 32 + lane];
        float a3 = adj[(size_t)(w + 3) * 32 + lane];
        unsigned m0 = __ballot_sync(0xffffffffu, a0 == 1.0f);
        unsigned m1 = __ballot_sync(0xffffffffu, a1 == 1.0f);
        unsigned m2 = __ballot_sync(0xffffffffu, a2 == 1.0f);
        unsigned m3 = __ballot_sync(0xffffffffu, a3 == 1.0f);
        if (lane == 0) *(uint4*)&g_bits[w] = make_uint4(m0, m1, m2, m3);
    }

    // ===== phase 1b: per-node h + factor pairs =====
    for (int idx = bid * NTHR + tid; idx < 6 * E; idx += NBLK * NTHR) {
        int c = idx >> 11, i = idx & 2047;
        int g = (c >= 3);
        int t = g ? c - 3 : c;
        const float* W  = (g ? Wt2 : Wt1) + t * 192;
        const float* av = (g ? at2 : at1) + t * 12;
        const float4* xv = (const float4*)((g ? uv : node) + i * 32);  // batch 0
        float h[6] = {0.f, 0.f, 0.f, 0.f, 0.f, 0.f};
#pragma unroll
        for (int k4 = 0; k4 < 8; k4++) {
            float4 xq = __ldg(&xv[k4]);
            const float* xf = (const float*)&xq;
#pragma unroll
            for (int q = 0; q < 4; q++) {
                int k = k4 * 4 + q;
#pragma unroll
                for (int d = 0; d < 6; d++)
                    h[d] = fmaf(xf[q], __ldg(&W[k * 6 + d]), h[d]);
            }
        }
        float e1 = 0.f, e2 = 0.f;
#pragma unroll
        for (int d = 0; d < 6; d++) {
            e1 = fmaf(h[d], __ldg(&av[d]), e1);
            e2 = fmaf(h[d], __ldg(&av[6 + d]), e2);
        }
        int gi = c * E + i;
        g_m1[gi]  = pack2(__expf(e1), __expf(0.2f * e1));
        g_PN[gi]  = pack2(__expf(e2), __expf(0.2f * e2));
        g_h01[gi] = pack2(h[0], h[1]);
        g_h23[gi] = pack2(h[2], h[3]);
        g_h45[gi] = pack2(h[4], h[5]);
    }
    gsync(base, 1);

    // ===== phase 2: softmax denominators (4096 tasks: row x half-combo, bits) =====
    for (int task = gwarp; task < 4096; task += NWARPS) {
        int r  = task >> 1;
        int c0 = (task & 1) * 3;
        ull mk[3]; float acc[3];
#pragma unroll
        for (int cc = 0; cc < 3; cc++) { mk[cc] = g_m1[(c0 + cc) * E + r]; acc[cc] = 0.f; }
        const unsigned* brow = &g_bits[r * 64];
        int wsel = lane >> 3;
        int bsh  = (lane & 7) * 4;
        for (int it = 0; it < 16; it++) {
            int j = it * 128 + lane * 4;
            unsigned b4 = (brow[it * 4 + wsel] >> bsh) & 0xFu;
            float av0 = (b4 & 1u) ? 1.f : 0.f;
            float av1 = (b4 & 2u) ? 1.f : 0.f;
            float av2 = (b4 & 4u) ? 1.f : 0.f;
            float av3 = (b4 & 8u) ? 1.f : 0.f;
#pragma unroll
            for (int cc = 0; cc < 3; cc++) {
                int c = c0 + cc;
                ulonglong2 pn01 = *(const ulonglong2*)&g_PN[c * E + j];
                ulonglong2 pn23 = *(const ulonglong2*)&g_PN[c * E + j + 2];
                float2 t;
                t = unpack2(mul2(mk[cc], pn01.x)); acc[cc] = fmaf(av0, fmaxf(t.x, t.y), acc[cc]);
                t = unpack2(mul2(mk[cc], pn01.y)); acc[cc] = fmaf(av1, fmaxf(t.x, t.y), acc[cc]);
                t = unpack2(mul2(mk[cc], pn23.x)); acc[cc] = fmaf(av2, fmaxf(t.x, t.y), acc[cc]);
                t = unpack2(mul2(mk[cc], pn23.y)); acc[cc] = fmaf(av3, fmaxf(t.x, t.y), acc[cc]);
            }
        }
#pragma unroll
        for (int cc = 0; cc < 3; cc++) {
            float v = acc[cc];
            for (int off = 16; off; off >>= 1) v += __shfl_down_sync(0xffffffffu, v, off);
            if (lane == 0) {
                int c = c0 + cc;
                float inv = 1.0f / v;
                float2 m = unpack2(mk[cc]);
                ulonglong4 nd;
                nd.x = pack2(m.x * inv, m.y * inv);
                nd.y = g_h01[c * E + r];
                nd.z = g_h23[c * E + r];
                nd.w = g_h45[c * E + r];
                g_nd[c * E + r] = nd;
            }
        }
    }
    gsync(base, 2);

    // ===== phase 3: attention aggregation (4608 tasks, bits) =====
    for (int task = gwarp; task < 4608; task += NWARPS) {
        int c    = task % 6;
        int jt   = (task / 6) & 31;
        int slab = task / 192;
        int j0 = jt * 64 + lane * 2;
        int ib = slab * 84;
        int iend = (slab == 23) ? 2048 : ib + 84;

        ull PNa = __ldg(&g_PN[c * E + j0]);
        ull PNb = __ldg(&g_PN[c * E + j0 + 1]);
        int bwi = jt * 2 + (lane >> 4);
        int bsh = (lane & 15) * 2;

        ull acc[6];
#pragma unroll
        for (int q = 0; q < 6; q++) acc[q] = 0;

#pragma unroll 1
        for (int ii = ib; ii < iend; ii += 4) {
            unsigned bq[4];
#pragma unroll
            for (int u = 0; u < 4; u++) bq[u] = g_bits[(ii + u) * 64 + bwi];
#pragma unroll
            for (int u = 0; u < 4; u++) {
                ulonglong4 nd = g_nd[c * E + ii + u];
                unsigned b2 = (bq[u] >> bsh) & 3u;
                float2 t0 = unpack2(mul2(nd.x, PNa));
                float w0 = (b2 & 1u) ? fmaxf(t0.x, t0.y) : 0.0f;
                ull w0p = pack2(w0, w0);
                ffma2(acc[0], w0p, nd.y);
                ffma2(acc[1], w0p, nd.z);
                ffma2(acc[2], w0p, nd.w);
                float2 t1 = unpack2(mul2(nd.x, PNb));
                float w1 = (b2 & 2u) ? fmaxf(t1.x, t1.y) : 0.0f;
                ull w1p = pack2(w1, w1);
                ffma2(acc[3], w1p, nd.y);
                ffma2(acc[4], w1p, nd.z);
                ffma2(acc[5], w1p, nd.w);
            }
        }

        int bse = slab * 36 + c * 6;
#pragma unroll
        for (int p = 0; p < 3; p++) {
            float2 tj0 = unpack2(acc[p]), tj1 = unpack2(acc[3 + p]);
            *(float2*)&g_part[(size_t)(bse + 2 * p) * E + j0]     = make_float2(tj0.x, tj1.x);
            *(float2*)&g_part[(size_t)(bse + 2 * p + 1) * E + j0] = make_float2(tj0.y, tj1.y);
        }
    }
    gsync(base, 3);

    // ===== phase 4: slab-reduce + ELU + XW  (64 tiles) =====
    for (int tile = bid; tile < 64; tile += NBLK) {
        int j0 = tile * 32;
        float* sh = s_u;              // [36][33]
        float* sW0 = s_u + 1188;
        float* sW1 = s_u + 1476;
        for (int t = tid; t < 288; t += NTHR) {
            sW0[t] = __ldg(&Wg1[t]);
            sW1[t] = __ldg(&Wo1[t]);
        }
        for (int t = tid; t < 36 * 32; t += NTHR) {
            int cd = t >> 5, jj = t & 31;
            int j = j0 + jj;
            float s = 0.f;
            for (int sl = 0; sl < NSLAB; sl++)
                s += g_part[(size_t)(sl * 36 + cd) * E + j];
            sh[cd * 33 + jj] = s > 0.f ? s : expm1f(s);
        }
        __syncthreads();
        for (int o = tid; o < 1024; o += NTHR) {
            int c = o >> 5, jj = o & 31;
            int g = c >> 4, cc = c & 15;
            const float* sW = g ? sW1 : sW0;
            float s = 0.f;
#pragma unroll
            for (int k = 0; k < 18; k++)
                s = fmaf(sh[(g * 18 + k) * 33 + jj], sW[k * 16 + cc], s);
            g_XW[(j0 + jj) * 32 + c] = s;
        }
        __syncthreads();
    }
    gsync(base, 4);

    // ===== phase 5: a0 @ XW via bitmask A (512 tasks: 16 r-tiles x 32 k-slices) =====
    for (int task = bid; task < 512; task += NBLK) {
        int r0 = (task & 15) * 128;
        int ks = task >> 4;
        int k0 = ks * 64;
        float* Bs = s_u;              // 64 x 32
        for (int t = tid; t < 2048; t += NTHR) Bs[t] = g_XW[k0 * 32 + t];
        __syncthreads();

        int rr = r0 + (tid >> 3) * 4;
        int cg = (tid & 7) * 4;
        float acc[16];
#pragma unroll
        for (int q = 0; q < 16; q++) acc[q] = 0.f;

#pragma unroll
        for (int chunk = 0; chunk < 2; chunk++) {
            unsigned w[4];
#pragma unroll
            for (int u = 0; u < 4; u++)
                w[u] = g_bits[(rr + u) * 64 + ks * 2 + chunk];
#pragma unroll 8
            for (int kk = 0; kk < 32; kk++) {
                float4 b = *(const float4*)&Bs[(chunk * 32 + kk) * 32 + cg];
#pragma unroll
                for (int u = 0; u < 4; u++) {
                    if ((w[u] >> kk) & 1u) {
                        acc[u * 4 + 0] += b.x;
                        acc[u * 4 + 1] += b.y;
                        acc[u * 4 + 2] += b.z;
                        acc[u * 4 + 3] += b.w;
                    }
                }
            }
        }
#pragma unroll
        for (int u = 0; u < 4; u++)
            *(float4*)&g_G1p[((size_t)ks * E + rr + u) * 32 + cg] =
                make_float4(acc[u * 4], acc[u * 4 + 1], acc[u * 4 + 2], acc[u * 4 + 3]);
        __syncthreads();
    }
    gsync(base, 5);

    // ===== phase 6: warp-per-j k-slice reduce + bias/relu + layer-2 =====
    for (int j = gwarp; j < E; j += NWARPS) {
        float y = 0.f;
#pragma unroll
        for (int ks = 0; ks < 32; ks++)
            y += g_G1p[((size_t)ks * E + j) * 32 + lane];
        y += (lane < 16) ? __ldg(&bg1[lane]) : __ldg(&bo1[lane - 16]);
        y = y > 0.f ? y : 0.f;
        int cc = lane & 15;
        const float* W2 = (lane < 16) ? Wg2 : Wo2;
        float zA = y * __ldg(&W2[cc * 2]);
        float zB = y * __ldg(&W2[cc * 2 + 1]);
#pragma unroll
        for (int off = 8; off; off >>= 1) {
            zA += __shfl_xor_sync(0xffffffffu, zA, off);
            zB += __shfl_xor_sync(0xffffffffu, zB, off);
        }
        if (lane == 0)  ((float2*)&g_Z[j])[0] = make_float2(zA, zB);
        if (lane == 16) ((float2*)&g_Z[j])[1] = make_float2(zA, zB);
    }
    gsync(base, 6);

    // ===== phase 7: a0 @ Z + bias, log_softmax / leaky (bits + Z in smem) =====
    {
        float4* sZ = (float4*)s_u;    // 2048 float4 = 32 KB
        for (int t = tid; t < E; t += NTHR) sZ[t] = g_Z[t];
        __syncthreads();
        for (int r = gwarp; r < E; r += NWARPS) {
            float a0 = 0.f, a1 = 0.f, a2 = 0.f, a3 = 0.f;
            const unsigned* brow = &g_bits[r * 64];
#pragma unroll 1
            for (int q = 0; q < 64; q += 4) {
                unsigned bw[4];
#pragma unroll
                for (int u = 0; u < 4; u++) bw[u] = brow[q + u];
#pragma unroll
                for (int u = 0; u < 4; u++) {
                    float4 z = sZ[(q + u) * 32 + lane];
                    if ((bw[u] >> lane) & 1u) {
                        a0 += z.x; a1 += z.y; a2 += z.z; a3 += z.w;
                    }
                }
            }
            for (int off = 16; off; off >>= 1) {
                a0 += __shfl_down_sync(0xffffffffu, a0, off);
                a1 += __shfl_down_sync(0xffffffffu, a1, off);
                a2 += __shfl_down_sync(0xffffffffu, a2, off);
                a3 += __shfl_down_sync(0xffffffffu, a3, off);
            }
            if (lane == 0) {
                float y0 = a0 + __ldg(&bg2[0]), y1 = a1 + __ldg(&bg2[1]);
                float m = fmaxf(y0, y1);
                float l = m + logf(expf(y0 - m) + expf(y1 - m));
                out[r * 2 + 0] = y0 - l;
                out[r * 2 + 1] = y1 - l;
                float o0 = a2 + __ldg(&bo2[0]), o1 = a3 + __ldg(&bo2[1]);
                out[2 * E + r * 2 + 0] = o0 > 0.f ? o0 : 0.01f * o0;
                out[2 * E + r * 2 + 1] = o1 > 0.f ? o1 : 0.01f * o1;
            }
        }
    }
}

// ---------------- launch ----------------
extern "C" void kernel_launch(void* const* d_in, const int* in_sizes, int n_in,
                              void* d_out, int out_size)
{
    (void)in_sizes; (void)n_in; (void)out_size;
    mega<<<NBLK, NTHR>>>(
        (const float*)d_in[0], (const float*)d_in[1], (const float*)d_in[2],
        (const float*)d_in[3], (const float*)d_in[4],
        (const float*)d_in[5], (const float*)d_in[6],
        (const float*)d_in[7], (const float*)d_in[8],
        (const float*)d_in[9], (const float*)d_in[10],
        (const float*)d_in[11], (const float*)d_in[12],
        (const float*)d_in[13], (const float*)d_in[14],
        (float*)d_out);
}